// round 10
// baseline (speedup 1.0000x reference)
#include <cuda_runtime.h>

#define N_NODES 50000
#define N_EDGES 800000
#define HIDDEN 64
#define OUT_DIM 16
#define NBLK 592          // 4 blocks/SM x 148 SMs
#define TPB 256
#define GSTRIDE (NBLK * TPB)
#define CHUNK 85          // ceil(50000/592)
#define TILE_N 64
#define NTILES 782        // ceil(50000/64)
#define SROW 132          // padded feature row: 128 data + 4 pad (528B, 16B-aligned)

// ---------------- device scratch ----------------
__device__ int g_count[N_NODES];
__device__ int g_off[N_NODES + 1];
__device__ int g_csr[N_EDGES];
__device__ int g_blocksum[NBLK];
__device__ int g_blockoff[NBLK];
__device__ unsigned g_bar_cnt;
__device__ unsigned g_bar_gen;
__device__ __align__(16) float g_h0[N_NODES * HIDDEN];
__device__ __align__(16) float g_h1[N_NODES * HIDDEN];
// packed pair-weights: per layer, [64 kpairs][64 f] of float2  (k<64 -> Wl, k>=64 -> Wr)
__device__ __align__(16) float g_wpack[3 * 64 * 128];

// ---------------- software grid barrier ----------------
__device__ __forceinline__ void grid_barrier() {
    __syncthreads();
    if (threadIdx.x == 0) {
        unsigned gen = *((volatile unsigned*)&g_bar_gen);
        __threadfence();
        unsigned a = atomicAdd(&g_bar_cnt, 1u);
        if (a == NBLK - 1) {
            g_bar_cnt = 0;
            __threadfence();
            atomicExch(&g_bar_gen, gen + 1u);
        } else {
            while (*((volatile unsigned*)&g_bar_gen) == gen) { __nanosleep(32); }
        }
        __threadfence();
    }
    __syncthreads();
}

// ---------------- packed f32x2 helpers ----------------
__device__ __forceinline__ unsigned long long fma_x2(
    unsigned long long a, unsigned long long b, unsigned long long c) {
    unsigned long long d;
    asm("fma.rn.f32x2 %0, %1, %2, %3;" : "=l"(d) : "l"(a), "l"(b), "l"(c));
    return d;
}
__device__ __forceinline__ float hsum2(unsigned long long a) {
    float lo, hi;
    asm("mov.b64 {%0, %1}, %2;" : "=f"(lo), "=f"(hi) : "l"(a));
    return lo + hi;
}
__device__ __forceinline__ void acc4(float4& a, float4 v) {
    a.x += v.x; a.y += v.y; a.z += v.z; a.w += v.w;
}
__device__ __forceinline__ float4 fma4(float s, float4 w, float4 acc) {
    acc.x = fmaf(s, w.x, acc.x);
    acc.y = fmaf(s, w.y, acc.y);
    acc.z = fmaf(s, w.z, acc.z);
    acc.w = fmaf(s, w.w, acc.w);
    return acc;
}

// ---------------- gather-mean (R8 version: 4-deep index prefetch, __ldg) ----------------
__device__ __forceinline__ float4 gather_mean(const float4* __restrict__ x4,
                                              int node, int q) {
    int s = __ldg(&g_off[node]);
    int e = __ldg(&g_off[node + 1]);
    float4 acc = make_float4(0.f, 0.f, 0.f, 0.f);
    int i = s;
    int i0 = 0, i1 = 0, i2 = 0, i3 = 0;
    if (i + 4 <= e) {
        i0 = __ldg(&g_csr[i]);     i1 = __ldg(&g_csr[i + 1]);
        i2 = __ldg(&g_csr[i + 2]); i3 = __ldg(&g_csr[i + 3]);
    }
    while (i + 4 <= e) {
        float4 v0 = __ldg(&x4[i0 * 16 + q]);
        float4 v1 = __ldg(&x4[i1 * 16 + q]);
        float4 v2 = __ldg(&x4[i2 * 16 + q]);
        float4 v3 = __ldg(&x4[i3 * 16 + q]);
        i += 4;
        if (i + 4 <= e) {
            i0 = __ldg(&g_csr[i]);     i1 = __ldg(&g_csr[i + 1]);
            i2 = __ldg(&g_csr[i + 2]); i3 = __ldg(&g_csr[i + 3]);
        }
        acc4(acc, v0); acc4(acc, v1); acc4(acc, v2); acc4(acc, v3);
    }
    for (; i < e; i++) {
        int s0 = __ldg(&g_csr[i]);
        float4 v = __ldg(&x4[s0 * 16 + q]);
        acc4(acc, v);
    }
    int deg = e - s;
    float invd = 1.0f / (float)(deg > 0 ? deg : 1);
    acc.x *= invd; acc.y *= invd; acc.z *= invd; acc.w *= invd;
    return acc;
}

// ---------------- one 64-node tile (packed f32x2 GEMM) ----------------
template <bool FINAL>
__device__ __forceinline__ void layer_tile(
    const float* __restrict__ xin,
    const float* __restrict__ wp,    // packed [64 kp][64 f] float2 for this layer
    const float* __restrict__ Wog,   // [64][16] (FINAL)
    const float* __restrict__ bl,
    const float* __restrict__ bout,
    float* __restrict__ dst,
    int tile, int tid, float* sFeat) {
    int node0 = tile * TILE_N;
    // gather: sFeat[n][0:64]=agg, [64:128]=x
    {
        int ln = tid >> 4, q = tid & 15;
        const float4* x4 = (const float4*)xin;
#pragma unroll
        for (int sub = 0; sub < 4; sub++) {
            int n = sub * 16 + ln;
            int node = node0 + n;
            float4 agg = make_float4(0.f, 0.f, 0.f, 0.f);
            float4 xv = agg;
            if (node < N_NODES) {
                agg = gather_mean(x4, node, q);
                xv = __ldg(&x4[node * 16 + q]);
            }
            *(float4*)&sFeat[n * SROW + q * 4] = agg;
            *(float4*)&sFeat[n * SROW + 64 + q * 4] = xv;
        }
    }
    __syncthreads();

    // GEMM: 4 nodes x 4 features per thread, K=128, packed-pair accumulation.
    int f0 = (tid & 15) * 4;
    int ngrp = tid >> 4;
    const float* r0 = &sFeat[(ngrp * 4 + 0) * SROW];
    const float* r1 = r0 + SROW;
    const float* r2 = r0 + 2 * SROW;
    const float* r3 = r0 + 3 * SROW;

    unsigned long long c00 = 0, c01 = 0, c02 = 0, c03 = 0;
    unsigned long long c10 = 0, c11 = 0, c12 = 0, c13 = 0;
    unsigned long long c20 = 0, c21 = 0, c22 = 0, c23 = 0;
    unsigned long long c30 = 0, c31 = 0, c32 = 0, c33 = 0;

#pragma unroll 4
    for (int k4 = 0; k4 < 32; k4++) {
        ulonglong2 a0 = *(const ulonglong2*)&r0[k4 * 4];
        ulonglong2 a1 = *(const ulonglong2*)&r1[k4 * 4];
        ulonglong2 a2 = *(const ulonglong2*)&r2[k4 * 4];
        ulonglong2 a3 = *(const ulonglong2*)&r3[k4 * 4];
        {   // k-pair row 2*k4 (covers k = 4k4, 4k4+1), lanes .x of a*
            const float* wb = &wp[(2 * k4) * 128 + 2 * f0];
            ulonglong2 wA  = __ldg((const ulonglong2*)&wb[0]);
            ulonglong2 wA2 = __ldg((const ulonglong2*)&wb[4]);
            c00 = fma_x2(a0.x, wA.x, c00);  c01 = fma_x2(a0.x, wA.y, c01);
            c02 = fma_x2(a0.x, wA2.x, c02); c03 = fma_x2(a0.x, wA2.y, c03);
            c10 = fma_x2(a1.x, wA.x, c10);  c11 = fma_x2(a1.x, wA.y, c11);
            c12 = fma_x2(a1.x, wA2.x, c12); c13 = fma_x2(a1.x, wA2.y, c13);
            c20 = fma_x2(a2.x, wA.x, c20);  c21 = fma_x2(a2.x, wA.y, c21);
            c22 = fma_x2(a2.x, wA2.x, c22); c23 = fma_x2(a2.x, wA2.y, c23);
            c30 = fma_x2(a3.x, wA.x, c30);  c31 = fma_x2(a3.x, wA.y, c31);
            c32 = fma_x2(a3.x, wA2.x, c32); c33 = fma_x2(a3.x, wA2.y, c33);
        }
        {   // k-pair row 2*k4+1 (covers k = 4k4+2, 4k4+3), lanes .y of a*
            const float* wb = &wp[(2 * k4 + 1) * 128 + 2 * f0];
            ulonglong2 wB  = __ldg((const ulonglong2*)&wb[0]);
            ulonglong2 wB2 = __ldg((const ulonglong2*)&wb[4]);
            c00 = fma_x2(a0.y, wB.x, c00);  c01 = fma_x2(a0.y, wB.y, c01);
            c02 = fma_x2(a0.y, wB2.x, c02); c03 = fma_x2(a0.y, wB2.y, c03);
            c10 = fma_x2(a1.y, wB.x, c10);  c11 = fma_x2(a1.y, wB.y, c11);
            c12 = fma_x2(a1.y, wB2.x, c12); c13 = fma_x2(a1.y, wB2.y, c13);
            c20 = fma_x2(a2.y, wB.x, c20);  c21 = fma_x2(a2.y, wB.y, c21);
            c22 = fma_x2(a2.y, wB2.x, c22); c23 = fma_x2(a2.y, wB2.y, c23);
            c30 = fma_x2(a3.y, wB.x, c30);  c31 = fma_x2(a3.y, wB.y, c31);
            c32 = fma_x2(a3.y, wB2.x, c32); c33 = fma_x2(a3.y, wB2.y, c33);
        }
    }

    float4 bias;
    bias.x = __ldg(&bl[f0]); bias.y = __ldg(&bl[f0 + 1]);
    bias.z = __ldg(&bl[f0 + 2]); bias.w = __ldg(&bl[f0 + 3]);
    float4 acc0, acc1, acc2, acc3;
    acc0.x = fmaxf(hsum2(c00) + bias.x, 0.f);
    acc0.y = fmaxf(hsum2(c01) + bias.y, 0.f);
    acc0.z = fmaxf(hsum2(c02) + bias.z, 0.f);
    acc0.w = fmaxf(hsum2(c03) + bias.w, 0.f);
    acc1.x = fmaxf(hsum2(c10) + bias.x, 0.f);
    acc1.y = fmaxf(hsum2(c11) + bias.y, 0.f);
    acc1.z = fmaxf(hsum2(c12) + bias.z, 0.f);
    acc1.w = fmaxf(hsum2(c13) + bias.w, 0.f);
    acc2.x = fmaxf(hsum2(c20) + bias.x, 0.f);
    acc2.y = fmaxf(hsum2(c21) + bias.y, 0.f);
    acc2.z = fmaxf(hsum2(c22) + bias.z, 0.f);
    acc2.w = fmaxf(hsum2(c23) + bias.w, 0.f);
    acc3.x = fmaxf(hsum2(c30) + bias.x, 0.f);
    acc3.y = fmaxf(hsum2(c31) + bias.y, 0.f);
    acc3.z = fmaxf(hsum2(c32) + bias.z, 0.f);
    acc3.w = fmaxf(hsum2(c33) + bias.w, 0.f);

    int nb = ngrp * 4;
    if (!FINAL) {
        int gn = node0 + nb;
        if (gn + 0 < N_NODES) *(float4*)&dst[(gn + 0) * 64 + f0] = acc0;
        if (gn + 1 < N_NODES) *(float4*)&dst[(gn + 1) * 64 + f0] = acc1;
        if (gn + 2 < N_NODES) *(float4*)&dst[(gn + 2) * 64 + f0] = acc2;
        if (gn + 3 < N_NODES) *(float4*)&dst[(gn + 3) * 64 + f0] = acc3;
        __syncthreads();
    } else {
        __syncthreads();
        *(float4*)&sFeat[(nb + 0) * SROW + f0] = acc0;
        *(float4*)&sFeat[(nb + 1) * SROW + f0] = acc1;
        *(float4*)&sFeat[(nb + 2) * SROW + f0] = acc2;
        *(float4*)&sFeat[(nb + 3) * SROW + f0] = acc3;
        __syncthreads();
        int n = tid >> 2;
        int o0 = (tid & 3) * 4;
        float4 oacc;
        oacc.x = __ldg(&bout[o0]); oacc.y = __ldg(&bout[o0 + 1]);
        oacc.z = __ldg(&bout[o0 + 2]); oacc.w = __ldg(&bout[o0 + 3]);
        const float* yr = &sFeat[n * SROW];
#pragma unroll 4
        for (int k4 = 0; k4 < 16; k4++) {
            float4 yv = *(const float4*)&yr[k4 * 4];
            const float* wb = &Wog[k4 * 64 + o0];
            float4 w0 = __ldg((const float4*)&wb[0]);
            float4 w1 = __ldg((const float4*)&wb[16]);
            float4 w2 = __ldg((const float4*)&wb[32]);
            float4 w3 = __ldg((const float4*)&wb[48]);
            oacc = fma4(yv.x, w0, oacc); oacc = fma4(yv.y, w1, oacc);
            oacc = fma4(yv.z, w2, oacc); oacc = fma4(yv.w, w3, oacc);
        }
        int gn = node0 + n;
        if (gn < N_NODES) *(float4*)&dst[gn * OUT_DIM + o0] = oacc;
        __syncthreads();
    }
}

// ---------------- persistent kernel ----------------
__global__ void __launch_bounds__(TPB, 4) fused_kernel(
    const float* __restrict__ x, const int* __restrict__ ei,
    const float* __restrict__ Wl, const float* __restrict__ bl,
    const float* __restrict__ Wr, const float* __restrict__ Wout,
    const float* __restrict__ bout, float* __restrict__ out) {
    __shared__ float sFeat[TILE_N * SROW];   // 33.8 KB
    __shared__ int sInts[8];

    int tid = threadIdx.x;
    int b = blockIdx.x;
    int gtid = b * TPB + tid;
    int lane = tid & 31, w = tid >> 5;

    // phase 0: zero counts + build packed pair-weights
    for (int i = gtid; i < N_NODES; i += GSTRIDE) g_count[i] = 0;
    for (int i = gtid; i < 3 * 64 * 64; i += GSTRIDE) {
        int l = i >> 12;           // layer
        int r = i & 4095;
        int kp = r >> 6;           // k-pair 0..63
        int f = r & 63;
        const float* WlL = Wl + l * 4096;
        const float* WrL = Wr + l * 4096;
        int k0 = 2 * kp;
        float v0, v1;
        if (kp < 32) { v0 = __ldg(&WlL[k0 * 64 + f]); v1 = __ldg(&WlL[(k0 + 1) * 64 + f]); }
        else { v0 = __ldg(&WrL[(k0 - 64) * 64 + f]); v1 = __ldg(&WrL[(k0 - 63) * 64 + f]); }
        *(float2*)&g_wpack[l * 8192 + kp * 128 + 2 * f] = make_float2(v0, v1);
    }
    grid_barrier();

    // phase 1: histogram
    {
        const int4* dst4 = (const int4*)(ei + N_EDGES);
        for (int t = gtid; t < N_EDGES / 4; t += GSTRIDE) {
            int4 d = __ldg(&dst4[t]);
            atomicAdd(&g_count[d.x], 1);
            atomicAdd(&g_count[d.y], 1);
            atomicAdd(&g_count[d.z], 1);
            atomicAdd(&g_count[d.w], 1);
        }
    }
    grid_barrier();

    // phase 2a: block-local exclusive scan of CHUNK counts
    {
        int base = b * CHUNK;
        int idx = base + tid;
        int v = (tid < CHUNK && idx < N_NODES) ? g_count[idx] : 0;
        int s = v;
#pragma unroll
        for (int d = 1; d < 32; d <<= 1) {
            int tv = __shfl_up_sync(0xffffffffu, s, d);
            if (lane >= d) s += tv;
        }
        if (lane == 31) sInts[w] = s;
        __syncthreads();
        if (tid == 0) {
            int acc = 0;
#pragma unroll
            for (int k = 0; k < 8; k++) { int t2 = sInts[k]; sInts[k] = acc; acc += t2; }
        }
        __syncthreads();
        int incl = s + sInts[w];
        if (tid < CHUNK && idx < N_NODES) g_off[idx] = incl - v;
        if (tid == TPB - 1) g_blocksum[b] = incl;
    }
    grid_barrier();

    // phase 2b: block 0 scans the NBLK block sums (3 per thread)
    if (b == 0) {
        int base2 = tid * 3;
        int v0 = (base2 + 0 < NBLK) ? g_blocksum[base2 + 0] : 0;
        int v1 = (base2 + 1 < NBLK) ? g_blocksum[base2 + 1] : 0;
        int v2 = (base2 + 2 < NBLK) ? g_blocksum[base2 + 2] : 0;
        int tsum = v0 + v1 + v2;
        int s = tsum;
#pragma unroll
        for (int d = 1; d < 32; d <<= 1) {
            int tv = __shfl_up_sync(0xffffffffu, s, d);
            if (lane >= d) s += tv;
        }
        if (lane == 31) sInts[w] = s;
        __syncthreads();
        if (tid == 0) {
            int acc = 0;
#pragma unroll
            for (int k = 0; k < 8; k++) { int t2 = sInts[k]; sInts[k] = acc; acc += t2; }
        }
        __syncthreads();
        int excl = (s - tsum) + sInts[w];
        if (base2 + 0 < NBLK) { g_blockoff[base2 + 0] = excl; excl += v0; }
        if (base2 + 1 < NBLK) { g_blockoff[base2 + 1] = excl; excl += v1; }
        if (base2 + 2 < NBLK) { g_blockoff[base2 + 2] = excl; excl += v2; }
    }
    grid_barrier();

    // phase 2c: add block offsets; init fill cursors
    {
        int off = g_blockoff[b];
        int idx = b * CHUNK + tid;
        if (tid < CHUNK && idx < N_NODES) {
            int o = g_off[idx] + off;
            g_off[idx] = o;
            g_count[idx] = o;
        }
        if (gtid == 0) g_off[N_NODES] = N_EDGES;
    }
    grid_barrier();

    // phase 3: fill CSR
    {
        const int4* src4 = (const int4*)ei;
        const int4* dst4 = (const int4*)(ei + N_EDGES);
        for (int t = gtid; t < N_EDGES / 4; t += GSTRIDE) {
            int4 sv = __ldg(&src4[t]);
            int4 d = __ldg(&dst4[t]);
            g_csr[atomicAdd(&g_count[d.x], 1)] = sv.x;
            g_csr[atomicAdd(&g_count[d.y], 1)] = sv.y;
            g_csr[atomicAdd(&g_count[d.z], 1)] = sv.z;
            g_csr[atomicAdd(&g_count[d.w], 1)] = sv.w;
        }
    }
    grid_barrier();

    // ---- layer 1: x -> g_h0 ----
    for (int tile = b; tile < NTILES; tile += NBLK)
        layer_tile<false>(x, g_wpack, Wout, bl, bout, g_h0, tile, tid, sFeat);
    grid_barrier();

    // ---- layer 2: g_h0 -> g_h1 ----
    for (int tile = b; tile < NTILES; tile += NBLK)
        layer_tile<false>(g_h0, g_wpack + 8192, Wout,
                          bl + HIDDEN, bout, g_h1, tile, tid, sFeat);
    grid_barrier();

    // ---- layer 3 + output projection: g_h1 -> out ----
    for (int tile = b; tile < NTILES; tile += NBLK)
        layer_tile<true>(g_h1, g_wpack + 16384, Wout,
                         bl + 2 * HIDDEN, bout, out, tile, tid, sFeat);
}

extern "C" void kernel_launch(void* const* d_in, const int* in_sizes, int n_in,
                              void* d_out, int out_size) {
    const float* x = (const float*)d_in[0];
    const int* ei = (const int*)d_in[1];
    const float* Wl = (const float*)d_in[2];
    const float* bl = (const float*)d_in[3];
    const float* Wr = (const float*)d_in[4];
    const float* Wout = (const float*)d_in[5];
    const float* bout = (const float*)d_in[6];
    float* out = (float*)d_out;

    fused_kernel<<<NBLK, TPB>>>(x, ei, Wl, bl, Wr, Wout, bout, out);
}

// round 11
// speedup vs baseline: 1.0214x; 1.0214x over previous
#include <cuda_runtime.h>

#define N_NODES 50000
#define N_EDGES 800000
#define HIDDEN 64
#define OUT_DIM 16
#define NBLK 888          // 6 blocks/SM x 148 SMs (exact)
#define TPB 128
#define GSTRIDE (NBLK * TPB)
#define CHUNK 57          // ceil(50000/888)
#define TILE_N 64
#define NTILES 782        // ceil(50000/64) < NBLK -> <=1 tile/block/layer
#define SROW 132          // padded feature row: 128 data + 4 pad

// ---------------- device scratch ----------------
__device__ int g_count[N_NODES];
__device__ int g_off[N_NODES + 1];
__device__ int g_csr[N_EDGES];
__device__ int g_blocksum[NBLK];
__device__ int g_blockoff[NBLK];
__device__ unsigned g_bar_cnt;
__device__ unsigned g_bar_gen;
__device__ __align__(16) float g_h0[N_NODES * HIDDEN];
__device__ __align__(16) float g_h1[N_NODES * HIDDEN];

// ---------------- software grid barrier ----------------
__device__ __forceinline__ void grid_barrier() {
    __syncthreads();
    if (threadIdx.x == 0) {
        unsigned gen = *((volatile unsigned*)&g_bar_gen);
        __threadfence();
        unsigned a = atomicAdd(&g_bar_cnt, 1u);
        if (a == NBLK - 1) {
            g_bar_cnt = 0;
            __threadfence();
            atomicExch(&g_bar_gen, gen + 1u);
        } else {
            while (*((volatile unsigned*)&g_bar_gen) == gen) { __nanosleep(32); }
        }
        __threadfence();
    }
    __syncthreads();
}

__device__ __forceinline__ float4 fma4(float s, float4 w, float4 acc) {
    acc.x = fmaf(s, w.x, acc.x);
    acc.y = fmaf(s, w.y, acc.y);
    acc.z = fmaf(s, w.z, acc.z);
    acc.w = fmaf(s, w.w, acc.w);
    return acc;
}
__device__ __forceinline__ float4 relu4(float4 v) {
    v.x = fmaxf(v.x, 0.f); v.y = fmaxf(v.y, 0.f);
    v.z = fmaxf(v.z, 0.f); v.w = fmaxf(v.w, 0.f);
    return v;
}
__device__ __forceinline__ void acc4(float4& a, float4 v) {
    a.x += v.x; a.y += v.y; a.z += v.z; a.w += v.w;
}

// ---------------- gather-mean (R8-proven: 4-deep index prefetch) ----------------
__device__ __forceinline__ float4 gather_mean(const float4* __restrict__ x4,
                                              int node, int q) {
    int s = __ldg(&g_off[node]);
    int e = __ldg(&g_off[node + 1]);
    float4 acc = make_float4(0.f, 0.f, 0.f, 0.f);
    int i = s;
    int i0 = 0, i1 = 0, i2 = 0, i3 = 0;
    if (i + 4 <= e) {
        i0 = __ldg(&g_csr[i]);     i1 = __ldg(&g_csr[i + 1]);
        i2 = __ldg(&g_csr[i + 2]); i3 = __ldg(&g_csr[i + 3]);
    }
    while (i + 4 <= e) {
        float4 v0 = __ldg(&x4[i0 * 16 + q]);
        float4 v1 = __ldg(&x4[i1 * 16 + q]);
        float4 v2 = __ldg(&x4[i2 * 16 + q]);
        float4 v3 = __ldg(&x4[i3 * 16 + q]);
        i += 4;
        if (i + 4 <= e) {
            i0 = __ldg(&g_csr[i]);     i1 = __ldg(&g_csr[i + 1]);
            i2 = __ldg(&g_csr[i + 2]); i3 = __ldg(&g_csr[i + 3]);
        }
        acc4(acc, v0); acc4(acc, v1); acc4(acc, v2); acc4(acc, v3);
    }
    for (; i < e; i++) {
        int s0 = __ldg(&g_csr[i]);
        float4 v = __ldg(&x4[s0 * 16 + q]);
        acc4(acc, v);
    }
    int deg = e - s;
    float invd = 1.0f / (float)(deg > 0 ? deg : 1);
    acc.x *= invd; acc.y *= invd; acc.z *= invd; acc.w *= invd;
    return acc;
}

// ---------------- one 64-node tile (TPB=128; GEMM 4 nodes x 8 features) ----------------
template <bool FINAL>
__device__ __forceinline__ void layer_tile(
    const float* __restrict__ xin,
    const float* __restrict__ Wlg,   // [64][64]
    const float* __restrict__ Wrg,   // [64][64]
    const float* __restrict__ Wog,   // [64][16] (FINAL)
    const float* __restrict__ bl,
    const float* __restrict__ bout,
    float* __restrict__ dst,
    int tile, int tid, float* sFeat) {
    int node0 = tile * TILE_N;
    // gather: 8 sub-rounds of 8 nodes (128 thr, 16/node); sFeat[n][0:64]=agg, [64:128]=x
    {
        int ln = tid >> 4, q = tid & 15;
        const float4* x4 = (const float4*)xin;
#pragma unroll
        for (int sub = 0; sub < 8; sub++) {
            int n = sub * 8 + ln;
            int node = node0 + n;
            float4 agg = make_float4(0.f, 0.f, 0.f, 0.f);
            float4 xv = agg;
            if (node < N_NODES) {
                agg = gather_mean(x4, node, q);
                xv = __ldg(&x4[node * 16 + q]);
            }
            *(float4*)&sFeat[n * SROW + q * 4] = agg;
            *(float4*)&sFeat[n * SROW + 64 + q * 4] = xv;
        }
    }
    __syncthreads();

    // GEMM: 4 nodes x 8 features per thread (16 node-groups x 8 f-groups = 128 thr)
    int f0 = (tid & 7) * 8;
    int ngrp = tid >> 3;
    const float* r0 = &sFeat[(ngrp * 4 + 0) * SROW];
    const float* r1 = r0 + SROW;
    const float* r2 = r0 + 2 * SROW;
    const float* r3 = r0 + 3 * SROW;

    float4 bA;
    bA.x = __ldg(&bl[f0]); bA.y = __ldg(&bl[f0 + 1]);
    bA.z = __ldg(&bl[f0 + 2]); bA.w = __ldg(&bl[f0 + 3]);
    float4 bB;
    bB.x = __ldg(&bl[f0 + 4]); bB.y = __ldg(&bl[f0 + 5]);
    bB.z = __ldg(&bl[f0 + 6]); bB.w = __ldg(&bl[f0 + 7]);
    float4 aA0 = bA, aA1 = bA, aA2 = bA, aA3 = bA;
    float4 aB0 = bB, aB1 = bB, aB2 = bB, aB3 = bB;

    // half 1: agg @ Wl (sFeat offset 0)
#pragma unroll 4
    for (int k4 = 0; k4 < 16; k4++) {
        float4 a0 = *(const float4*)&r0[k4 * 4];
        float4 a1 = *(const float4*)&r1[k4 * 4];
        float4 a2 = *(const float4*)&r2[k4 * 4];
        float4 a3 = *(const float4*)&r3[k4 * 4];
#pragma unroll
        for (int kk = 0; kk < 4; kk++) {
            const float* wr = &Wlg[(k4 * 4 + kk) * 64 + f0];
            float4 wA = __ldg((const float4*)&wr[0]);
            float4 wB = __ldg((const float4*)&wr[4]);
            float s0 = (&a0.x)[kk], s1 = (&a1.x)[kk], s2 = (&a2.x)[kk], s3 = (&a3.x)[kk];
            aA0 = fma4(s0, wA, aA0); aB0 = fma4(s0, wB, aB0);
            aA1 = fma4(s1, wA, aA1); aB1 = fma4(s1, wB, aB1);
            aA2 = fma4(s2, wA, aA2); aB2 = fma4(s2, wB, aB2);
            aA3 = fma4(s3, wA, aA3); aB3 = fma4(s3, wB, aB3);
        }
    }
    // half 2: x @ Wr (sFeat offset 64)
#pragma unroll 4
    for (int k4 = 0; k4 < 16; k4++) {
        float4 a0 = *(const float4*)&r0[64 + k4 * 4];
        float4 a1 = *(const float4*)&r1[64 + k4 * 4];
        float4 a2 = *(const float4*)&r2[64 + k4 * 4];
        float4 a3 = *(const float4*)&r3[64 + k4 * 4];
#pragma unroll
        for (int kk = 0; kk < 4; kk++) {
            const float* wr = &Wrg[(k4 * 4 + kk) * 64 + f0];
            float4 wA = __ldg((const float4*)&wr[0]);
            float4 wB = __ldg((const float4*)&wr[4]);
            float s0 = (&a0.x)[kk], s1 = (&a1.x)[kk], s2 = (&a2.x)[kk], s3 = (&a3.x)[kk];
            aA0 = fma4(s0, wA, aA0); aB0 = fma4(s0, wB, aB0);
            aA1 = fma4(s1, wA, aA1); aB1 = fma4(s1, wB, aB1);
            aA2 = fma4(s2, wA, aA2); aB2 = fma4(s2, wB, aB2);
            aA3 = fma4(s3, wA, aA3); aB3 = fma4(s3, wB, aB3);
        }
    }
    aA0 = relu4(aA0); aA1 = relu4(aA1); aA2 = relu4(aA2); aA3 = relu4(aA3);
    aB0 = relu4(aB0); aB1 = relu4(aB1); aB2 = relu4(aB2); aB3 = relu4(aB3);

    int nb = ngrp * 4;
    if (!FINAL) {
        int gn = node0 + nb;
        if (gn + 0 < N_NODES) {
            *(float4*)&dst[(gn + 0) * 64 + f0] = aA0;
            *(float4*)&dst[(gn + 0) * 64 + f0 + 4] = aB0;
        }
        if (gn + 1 < N_NODES) {
            *(float4*)&dst[(gn + 1) * 64 + f0] = aA1;
            *(float4*)&dst[(gn + 1) * 64 + f0 + 4] = aB1;
        }
        if (gn + 2 < N_NODES) {
            *(float4*)&dst[(gn + 2) * 64 + f0] = aA2;
            *(float4*)&dst[(gn + 2) * 64 + f0 + 4] = aB2;
        }
        if (gn + 3 < N_NODES) {
            *(float4*)&dst[(gn + 3) * 64 + f0] = aA3;
            *(float4*)&dst[(gn + 3) * 64 + f0 + 4] = aB3;
        }
        __syncthreads();
    } else {
        __syncthreads();
        *(float4*)&sFeat[(nb + 0) * SROW + f0] = aA0;
        *(float4*)&sFeat[(nb + 0) * SROW + f0 + 4] = aB0;
        *(float4*)&sFeat[(nb + 1) * SROW + f0] = aA1;
        *(float4*)&sFeat[(nb + 1) * SROW + f0 + 4] = aB1;
        *(float4*)&sFeat[(nb + 2) * SROW + f0] = aA2;
        *(float4*)&sFeat[(nb + 2) * SROW + f0 + 4] = aB2;
        *(float4*)&sFeat[(nb + 3) * SROW + f0] = aA3;
        *(float4*)&sFeat[(nb + 3) * SROW + f0 + 4] = aB3;
        __syncthreads();
        // output projection: n = tid>>1 (0..63), o0 = (tid&1)*8
        int n = tid >> 1;
        int o0 = (tid & 1) * 8;
        float4 oA, oB;
        oA.x = __ldg(&bout[o0]);     oA.y = __ldg(&bout[o0 + 1]);
        oA.z = __ldg(&bout[o0 + 2]); oA.w = __ldg(&bout[o0 + 3]);
        oB.x = __ldg(&bout[o0 + 4]); oB.y = __ldg(&bout[o0 + 5]);
        oB.z = __ldg(&bout[o0 + 6]); oB.w = __ldg(&bout[o0 + 7]);
        const float* yr = &sFeat[n * SROW];
#pragma unroll 4
        for (int k4 = 0; k4 < 16; k4++) {
            float4 yv = *(const float4*)&yr[k4 * 4];
#pragma unroll
            for (int kk = 0; kk < 4; kk++) {
                const float* wr = &Wog[(k4 * 4 + kk) * 16 + o0];
                float4 wA = __ldg((const float4*)&wr[0]);
                float4 wB = __ldg((const float4*)&wr[4]);
                float s = (&yv.x)[kk];
                oA = fma4(s, wA, oA);
                oB = fma4(s, wB, oB);
            }
        }
        int gn = node0 + n;
        if (gn < N_NODES) {
            *(float4*)&dst[gn * OUT_DIM + o0] = oA;
            *(float4*)&dst[gn * OUT_DIM + o0 + 4] = oB;
        }
        __syncthreads();
    }
}

// ---------------- persistent kernel ----------------
__global__ void __launch_bounds__(TPB, 6) fused_kernel(
    const float* __restrict__ x, const int* __restrict__ ei,
    const float* __restrict__ Wl, const float* __restrict__ bl,
    const float* __restrict__ Wr, const float* __restrict__ Wout,
    const float* __restrict__ bout, float* __restrict__ out) {
    __shared__ float sFeat[TILE_N * SROW];   // 33.8 KB
    __shared__ int sInts[4];

    int tid = threadIdx.x;
    int b = blockIdx.x;
    int gtid = b * TPB + tid;
    int lane = tid & 31, w = tid >> 5;

    // phase 0: zero counts
    for (int i = gtid; i < N_NODES; i += GSTRIDE) g_count[i] = 0;
    grid_barrier();

    // phase 1: histogram
    {
        const int4* dst4 = (const int4*)(ei + N_EDGES);
        for (int t = gtid; t < N_EDGES / 4; t += GSTRIDE) {
            int4 d = __ldg(&dst4[t]);
            atomicAdd(&g_count[d.x], 1);
            atomicAdd(&g_count[d.y], 1);
            atomicAdd(&g_count[d.z], 1);
            atomicAdd(&g_count[d.w], 1);
        }
    }
    grid_barrier();

    // phase 2a: block-local exclusive scan of CHUNK counts
    {
        int base = b * CHUNK;
        int idx = base + tid;
        int v = (tid < CHUNK && idx < N_NODES) ? g_count[idx] : 0;
        int s = v;
#pragma unroll
        for (int d = 1; d < 32; d <<= 1) {
            int tv = __shfl_up_sync(0xffffffffu, s, d);
            if (lane >= d) s += tv;
        }
        if (lane == 31) sInts[w] = s;
        __syncthreads();
        if (tid == 0) {
            int acc = 0;
#pragma unroll
            for (int k = 0; k < 4; k++) { int t2 = sInts[k]; sInts[k] = acc; acc += t2; }
        }
        __syncthreads();
        int incl = s + sInts[w];
        if (tid < CHUNK && idx < N_NODES) g_off[idx] = incl - v;
        if (tid == TPB - 1) g_blocksum[b] = incl;
    }
    grid_barrier();

    // phase 2b: block 0 scans the NBLK block sums (7 per thread)
    if (b == 0) {
        int base2 = tid * 7;
        int vv[7];
        int tsum = 0;
#pragma unroll
        for (int k = 0; k < 7; k++) {
            vv[k] = (base2 + k < NBLK) ? g_blocksum[base2 + k] : 0;
            tsum += vv[k];
        }
        int s = tsum;
#pragma unroll
        for (int d = 1; d < 32; d <<= 1) {
            int tv = __shfl_up_sync(0xffffffffu, s, d);
            if (lane >= d) s += tv;
        }
        if (lane == 31) sInts[w] = s;
        __syncthreads();
        if (tid == 0) {
            int acc = 0;
#pragma unroll
            for (int k = 0; k < 4; k++) { int t2 = sInts[k]; sInts[k] = acc; acc += t2; }
        }
        __syncthreads();
        int excl = (s - tsum) + sInts[w];
#pragma unroll
        for (int k = 0; k < 7; k++) {
            if (base2 + k < NBLK) { g_blockoff[base2 + k] = excl; excl += vv[k]; }
        }
    }
    grid_barrier();

    // phase 2c: add block offsets; init fill cursors
    {
        int off = g_blockoff[b];
        int idx = b * CHUNK + tid;
        if (tid < CHUNK && idx < N_NODES) {
            int o = g_off[idx] + off;
            g_off[idx] = o;
            g_count[idx] = o;
        }
        if (gtid == 0) g_off[N_NODES] = N_EDGES;
    }
    grid_barrier();

    // phase 3: fill CSR
    {
        const int4* src4 = (const int4*)ei;
        const int4* dst4 = (const int4*)(ei + N_EDGES);
        for (int t = gtid; t < N_EDGES / 4; t += GSTRIDE) {
            int4 sv = __ldg(&src4[t]);
            int4 d = __ldg(&dst4[t]);
            g_csr[atomicAdd(&g_count[d.x], 1)] = sv.x;
            g_csr[atomicAdd(&g_count[d.y], 1)] = sv.y;
            g_csr[atomicAdd(&g_count[d.z], 1)] = sv.z;
            g_csr[atomicAdd(&g_count[d.w], 1)] = sv.w;
        }
    }
    grid_barrier();

    // ---- layer 1: x -> g_h0 ----
    for (int tile = b; tile < NTILES; tile += NBLK)
        layer_tile<false>(x, Wl, Wr, Wout, bl, bout, g_h0, tile, tid, sFeat);
    grid_barrier();

    // ---- layer 2: g_h0 -> g_h1 ----
    for (int tile = b; tile < NTILES; tile += NBLK)
        layer_tile<false>(g_h0, Wl + 4096, Wr + 4096, Wout,
                          bl + HIDDEN, bout, g_h1, tile, tid, sFeat);
    grid_barrier();

    // ---- layer 3 + output projection: g_h1 -> out ----
    for (int tile = b; tile < NTILES; tile += NBLK)
        layer_tile<true>(g_h1, Wl + 8192, Wr + 8192, Wout,
                         bl + 2 * HIDDEN, bout, out, tile, tid, sFeat);
}

extern "C" void kernel_launch(void* const* d_in, const int* in_sizes, int n_in,
                              void* d_out, int out_size) {
    const float* x = (const float*)d_in[0];
    const int* ei = (const int*)d_in[1];
    const float* Wl = (const float*)d_in[2];
    const float* bl = (const float*)d_in[3];
    const float* Wr = (const float*)d_in[4];
    const float* Wout = (const float*)d_in[5];
    const float* bout = (const float*)d_in[6];
    float* out = (float*)d_out;

    fused_kernel<<<NBLK, TPB>>>(x, ei, Wl, bl, Wr, Wout, bout, out);
}